// round 1
// baseline (speedup 1.0000x reference)
#include <cuda_runtime.h>
#include <cuda_bf16.h>
#include <math.h>

// Problem dims
#define BB 64
#define LL 512
#define EE 256
#define HH 8
#define NN 32
#define DC 4
#define DI 512
#define DTR 16
#define MROWS (BB*LL)   // 32768

// ---------------- scratch (static device globals; no allocs) ----------------
__device__ float g_seqs  [MROWS*EE];
__device__ float g_xz    [MROWS*(2*DI)];
__device__ float g_uconv [MROWS*DI];
__device__ float g_xdbl  [MROWS*80];
__device__ float g_dt    [MROWS*DI];
__device__ float g_ymam  [MROWS*DI];
__device__ float g_mamba [MROWS*EE];
__device__ float g_qkv   [MROWS*(3*EE)];
__device__ float g_ctx   [MROWS*EE];
__device__ float g_attno [MROWS*EE];
__device__ float g_attnln[MROWS*EE];
__device__ float g_comb  [MROWS*EE];
__device__ float g_ffh   [MROWS*(4*EE)];
__device__ float g_ff    [MROWS*EE];
__device__ float g_feats [MROWS*EE];
__device__ float g_gate  [BB];

// ---------------- embedding + positional ----------------
__global__ void embed_kernel(const int* __restrict__ log_seqs,
                             const float* __restrict__ item_emb,
                             const float* __restrict__ pos_emb) {
    int i = blockIdx.x * blockDim.x + threadIdx.x;   // over MROWS*EE
    int row = i >> 8;           // b*L + l
    int e   = i & 255;
    int l   = row & (LL-1);
    int it  = __ldg(&log_seqs[row]);
    g_seqs[i] = item_emb[(size_t)it*EE + e] * 16.0f + pos_emb[l*EE + e];
}

// ---------------- generic fp32 GEMM: C = act(A[M,K](lda) * W[N,K]^T + bias) ----------------
// act: 0 none, 1 relu, 2 softplus
__global__ __launch_bounds__(256)
void sgemm_kernel(const float* __restrict__ A, int lda,
                  const float* __restrict__ W,
                  const float* __restrict__ bias,
                  float* __restrict__ C,
                  int M, int N, int K, int act) {
    const int BM=128, BN=128, BK=8;
    __shared__ float As[BK][BM];
    __shared__ float Ws[BK][BN];
    int tid = threadIdx.x;
    int tx = tid & 15, ty = tid >> 4;
    int m0 = blockIdx.y * BM;
    int n0 = blockIdx.x * BN;

    float acc[8][8];
    #pragma unroll
    for (int i=0;i<8;i++)
        #pragma unroll
        for (int j=0;j<8;j++) acc[i][j]=0.f;

    int lr = tid >> 1;          // 0..127
    int lc = (tid & 1) * 4;     // 0 or 4

    for (int k0 = 0; k0 < K; k0 += BK) {
        float4 a4 = *(const float4*)(A + (size_t)(m0+lr)*lda + k0 + lc);
        As[lc+0][lr]=a4.x; As[lc+1][lr]=a4.y; As[lc+2][lr]=a4.z; As[lc+3][lr]=a4.w;
        float4 w4 = make_float4(0.f,0.f,0.f,0.f);
        if (n0 + lr < N) w4 = *(const float4*)(W + (size_t)(n0+lr)*K + k0 + lc);
        Ws[lc+0][lr]=w4.x; Ws[lc+1][lr]=w4.y; Ws[lc+2][lr]=w4.z; Ws[lc+3][lr]=w4.w;
        __syncthreads();
        #pragma unroll
        for (int k=0;k<BK;k++) {
            float4 arA = *(const float4*)&As[k][ty*8];
            float4 arB = *(const float4*)&As[k][ty*8+4];
            float4 wrA = *(const float4*)&Ws[k][tx*8];
            float4 wrB = *(const float4*)&Ws[k][tx*8+4];
            float ar[8] = {arA.x,arA.y,arA.z,arA.w,arB.x,arB.y,arB.z,arB.w};
            float wr[8] = {wrA.x,wrA.y,wrA.z,wrA.w,wrB.x,wrB.y,wrB.z,wrB.w};
            #pragma unroll
            for (int i=0;i<8;i++)
                #pragma unroll
                for (int j=0;j<8;j++)
                    acc[i][j] = fmaf(ar[i], wr[j], acc[i][j]);
        }
        __syncthreads();
    }
    #pragma unroll
    for (int i=0;i<8;i++) {
        int m = m0 + ty*8 + i;
        #pragma unroll
        for (int j=0;j<8;j++) {
            int n = n0 + tx*8 + j;
            if (n < N) {
                float v = acc[i][j];
                if (bias) v += bias[n];
                if (act == 1) v = fmaxf(v, 0.f);
                else if (act == 2) v = (v > 20.f) ? v : log1pf(__expf(v));
                C[(size_t)m*N + n] = v;
            }
        }
    }
}

// ---------------- causal depthwise conv (DC=4) + SiLU ----------------
__global__ void conv_silu_kernel(const float* __restrict__ conv_w,
                                 const float* __restrict__ conv_b) {
    int i = blockIdx.x * blockDim.x + threadIdx.x;   // over MROWS*DI
    int row = i >> 9;           // b*L+l
    int d   = i & (DI-1);
    int b   = row >> 9;
    int l   = row & (LL-1);
    float acc = conv_b[d];
    #pragma unroll
    for (int k=0;k<DC;k++) {
        int ll = l - (DC-1) + k;
        if (ll >= 0)
            acc = fmaf(g_xz[(size_t)((b<<9)+ll)*(2*DI) + d], conv_w[d*DC + k], acc);
    }
    float s = acc / (1.f + __expf(-acc));   // silu
    g_uconv[i] = s;
}

// ---------------- selective scan: one warp per (b,d), lane = n ----------------
__global__ void scan_kernel(const float* __restrict__ A_log,
                            const float* __restrict__ Dp) {
    int warp = blockIdx.x * (blockDim.x >> 5) + (threadIdx.x >> 5);
    int lane = threadIdx.x & 31;
    int b = warp >> 9;          // DI=512
    int d = warp & (DI-1);
    float A  = -__expf(A_log[d*NN + lane]);
    float dp = Dp[d];
    float h = 0.f;
    for (int l = 0; l < LL; l++) {
        int row = (b<<9) + l;
        float dtv = g_dt[(size_t)row*DI + d];
        float uv  = g_uconv[(size_t)row*DI + d];
        float Bv  = g_xdbl[(size_t)row*80 + DTR + lane];
        float Cv  = g_xdbl[(size_t)row*80 + DTR + NN + lane];
        h = fmaf(__expf(dtv*A), h, dtv*Bv*uv);
        float y = h * Cv;
        #pragma unroll
        for (int off=16; off; off>>=1) y += __shfl_xor_sync(0xffffffffu, y, off);
        if (lane == 0) {
            float z  = g_xz[(size_t)row*(2*DI) + DI + d];
            float sz = z / (1.f + __expf(-z));
            g_ymam[(size_t)row*DI + d] = (y + uv*dp) * sz;
        }
    }
}

// ---------------- fused attention: block = (b,h), thread = query ----------------
__global__ __launch_bounds__(512)
void attn_kernel() {
    int b = blockIdx.x / HH, h = blockIdx.x % HH;
    __shared__ float Ks[64][32];
    __shared__ float Vs[64][32];
    int q = threadIdx.x;
    const float scale = 0.17677669529663687f;   // 1/sqrt(32)
    int rowq = (b<<9) + q;
    float qreg[32];
    {
        const float4* qp = (const float4*)(g_qkv + (size_t)rowq*(3*EE) + h*32);
        #pragma unroll
        for (int i=0;i<8;i++) {
            float4 v = qp[i];
            qreg[i*4+0]=v.x*scale; qreg[i*4+1]=v.y*scale;
            qreg[i*4+2]=v.z*scale; qreg[i*4+3]=v.w*scale;
        }
    }
    float m = -1e30f, lsum = 0.f;
    float o[32];
    #pragma unroll
    for (int i=0;i<32;i++) o[i]=0.f;

    for (int t=0; t<LL; t+=64) {
        __syncthreads();
        {
            int idx = threadIdx.x;
            int r = idx >> 3, c = (idx & 7) * 4;
            int rowk = (b<<9) + t + r;
            *(float4*)&Ks[r][c] = *(const float4*)(g_qkv + (size_t)rowk*(3*EE) + EE   + h*32 + c);
            *(float4*)&Vs[r][c] = *(const float4*)(g_qkv + (size_t)rowk*(3*EE) + 2*EE + h*32 + c);
        }
        __syncthreads();
        for (int j=0;j<64;j++) {
            float s = 0.f;
            const float4* kr = (const float4*)Ks[j];
            #pragma unroll
            for (int i=0;i<8;i++) {
                float4 k4 = kr[i];
                s = fmaf(qreg[i*4+0], k4.x, s); s = fmaf(qreg[i*4+1], k4.y, s);
                s = fmaf(qreg[i*4+2], k4.z, s); s = fmaf(qreg[i*4+3], k4.w, s);
            }
            if (s > m) {
                float corr = __expf(m - s);
                m = s;
                lsum *= corr;
                #pragma unroll
                for (int i=0;i<32;i++) o[i] *= corr;
            }
            float p = __expf(s - m);
            lsum += p;
            const float4* vr = (const float4*)Vs[j];
            #pragma unroll
            for (int i=0;i<8;i++) {
                float4 v4 = vr[i];
                o[i*4+0] = fmaf(p, v4.x, o[i*4+0]);
                o[i*4+1] = fmaf(p, v4.y, o[i*4+1]);
                o[i*4+2] = fmaf(p, v4.z, o[i*4+2]);
                o[i*4+3] = fmaf(p, v4.w, o[i*4+3]);
            }
        }
    }
    float inv = 1.f / lsum;
    float4* op = (float4*)(g_ctx + (size_t)rowq*EE + h*32);
    #pragma unroll
    for (int i=0;i<8;i++)
        op[i] = make_float4(o[i*4]*inv, o[i*4+1]*inv, o[i*4+2]*inv, o[i*4+3]*inv);
}

// ---------------- residual add + LayerNorm (warp per row, E=256) ----------------
__global__ void add_ln_kernel(const float* __restrict__ x, const float* __restrict__ res,
                              const float* __restrict__ g, const float* __restrict__ bta,
                              float* __restrict__ out) {
    int row  = blockIdx.x * (blockDim.x >> 5) + (threadIdx.x >> 5);
    int lane = threadIdx.x & 31;
    const float4* xp = (const float4*)(x   + (size_t)row*EE);
    const float4* rp = (const float4*)(res + (size_t)row*EE);
    float v[8];
    float4 a0 = xp[lane],     b0 = rp[lane];
    float4 a1 = xp[lane+32],  b1 = rp[lane+32];
    v[0]=a0.x+b0.x; v[1]=a0.y+b0.y; v[2]=a0.z+b0.z; v[3]=a0.w+b0.w;
    v[4]=a1.x+b1.x; v[5]=a1.y+b1.y; v[6]=a1.z+b1.z; v[7]=a1.w+b1.w;
    float s=0.f, s2=0.f;
    #pragma unroll
    for (int i=0;i<8;i++){ s += v[i]; s2 = fmaf(v[i], v[i], s2); }
    #pragma unroll
    for (int off=16; off; off>>=1) {
        s  += __shfl_xor_sync(0xffffffffu, s,  off);
        s2 += __shfl_xor_sync(0xffffffffu, s2, off);
    }
    float mean = s * (1.f/EE);
    float var  = s2 * (1.f/EE) - mean*mean;
    float rstd = rsqrtf(var + 1e-6f);
    float4* op = (float4*)(out + (size_t)row*EE);
    const float4* gp = (const float4*)g;
    const float4* bp = (const float4*)bta;
    float4 g0=gp[lane], g1=gp[lane+32], c0=bp[lane], c1=bp[lane+32];
    op[lane]    = make_float4((v[0]-mean)*rstd*g0.x+c0.x, (v[1]-mean)*rstd*g0.y+c0.y,
                              (v[2]-mean)*rstd*g0.z+c0.z, (v[3]-mean)*rstd*g0.w+c0.w);
    op[lane+32] = make_float4((v[4]-mean)*rstd*g1.x+c1.x, (v[5]-mean)*rstd*g1.y+c1.y,
                              (v[6]-mean)*rstd*g1.z+c1.z, (v[7]-mean)*rstd*g1.w+c1.w);
}

// ---------------- gate: sigmoid(mean_l(seqs) @ mw_w^T + mw_b) per batch ----------------
__global__ void gate_kernel(const float* __restrict__ mw_w, const float* __restrict__ mw_b) {
    int b = blockIdx.x;
    int e = threadIdx.x;           // 256 threads
    float s = 0.f;
    for (int l=0;l<LL;l++) s += g_seqs[(size_t)((b<<9)+l)*EE + e];
    s = (s * (1.f/LL)) * mw_w[e];
    __shared__ float red[256];
    red[e] = s; __syncthreads();
    for (int st=128; st; st>>=1) { if (e < st) red[e] += red[e+st]; __syncthreads(); }
    if (e == 0) g_gate[b] = 1.f / (1.f + __expf(-(red[0] + mw_b[0])));
}

// ---------------- gated combine ----------------
__global__ void combine_kernel() {
    int i = blockIdx.x * blockDim.x + threadIdx.x;   // over MROWS*EE
    int row = i >> 8;
    float w = g_gate[row >> 9];
    g_comb[i] = w * g_mamba[i] + (1.f - w) * g_attnln[i];
}

// ---------------- logits: warp per (b,l), pos & neg dots ----------------
__global__ void logits_kernel(const int* __restrict__ pos, const int* __restrict__ neg,
                              const float* __restrict__ item_emb, float* __restrict__ out) {
    int row  = blockIdx.x * (blockDim.x >> 5) + (threadIdx.x >> 5);
    int lane = threadIdx.x & 31;
    const float4* f = (const float4*)(g_feats + (size_t)row*EE);
    float4 f0 = f[lane], f1 = f[lane+32];
    int pi = __ldg(&pos[row]), ni = __ldg(&neg[row]);
    const float4* pe = (const float4*)(item_emb + (size_t)pi*EE);
    const float4* ne = (const float4*)(item_emb + (size_t)ni*EE);
    float4 p0 = pe[lane], p1 = pe[lane+32];
    float4 n0 = ne[lane], n1 = ne[lane+32];
    float dp = f0.x*p0.x+f0.y*p0.y+f0.z*p0.z+f0.w*p0.w
             + f1.x*p1.x+f1.y*p1.y+f1.z*p1.z+f1.w*p1.w;
    float dn = f0.x*n0.x+f0.y*n0.y+f0.z*n0.z+f0.w*n0.w
             + f1.x*n1.x+f1.y*n1.y+f1.z*n1.z+f1.w*n1.w;
    #pragma unroll
    for (int off=16; off; off>>=1) {
        dp += __shfl_xor_sync(0xffffffffu, dp, off);
        dn += __shfl_xor_sync(0xffffffffu, dn, off);
    }
    if (lane == 0) {
        out[row]         = dp;
        out[MROWS + row] = dn;
    }
}

// ---------------- host ----------------
static float* symaddr(const void* sym) {
    void* p = nullptr;
    cudaGetSymbolAddress(&p, sym);
    return (float*)p;
}

static void gemm(const float* A, int lda, const float* W, const float* bias,
                 float* C, int M, int N, int K, int act) {
    dim3 grid((N + 127) / 128, M / 128);
    sgemm_kernel<<<grid, 256>>>(A, lda, W, bias, C, M, N, K, act);
}

extern "C" void kernel_launch(void* const* d_in, const int* in_sizes, int n_in,
                              void* d_out, int out_size) {
    const int*   log_seqs  = (const int*)  d_in[1];
    const int*   pos_seqs  = (const int*)  d_in[2];
    const int*   neg_seqs  = (const int*)  d_in[3];
    const float* item_emb  = (const float*)d_in[4];
    const float* pos_emb   = (const float*)d_in[5];
    const float* in_proj_w = (const float*)d_in[6];
    const float* conv_w    = (const float*)d_in[7];
    const float* conv_b    = (const float*)d_in[8];
    const float* x_proj_w  = (const float*)d_in[9];
    const float* dt_proj_w = (const float*)d_in[10];
    const float* dt_proj_b = (const float*)d_in[11];
    const float* A_log     = (const float*)d_in[12];
    const float* Dp        = (const float*)d_in[13];
    const float* out_proj_w= (const float*)d_in[14];
    const float* attn_in_w = (const float*)d_in[15];
    const float* attn_in_b = (const float*)d_in[16];
    const float* attn_out_w= (const float*)d_in[17];
    const float* attn_out_b= (const float*)d_in[18];
    const float* ln1_g     = (const float*)d_in[19];
    const float* ln1_b     = (const float*)d_in[20];
    const float* mw_w      = (const float*)d_in[21];
    const float* mw_b      = (const float*)d_in[22];
    const float* ff_w1     = (const float*)d_in[23];
    const float* ff_b1     = (const float*)d_in[24];
    const float* ff_w2     = (const float*)d_in[25];
    const float* ff_b2     = (const float*)d_in[26];
    const float* ln2_g     = (const float*)d_in[27];
    const float* ln2_b     = (const float*)d_in[28];
    float* out = (float*)d_out;

    float* p_seqs   = symaddr(g_seqs);
    float* p_xz     = symaddr(g_xz);
    float* p_uconv  = symaddr(g_uconv);
    float* p_xdbl   = symaddr(g_xdbl);
    float* p_dt     = symaddr(g_dt);
    float* p_ymam   = symaddr(g_ymam);
    float* p_mamba  = symaddr(g_mamba);
    float* p_qkv    = symaddr(g_qkv);
    float* p_ctx    = symaddr(g_ctx);
    float* p_attno  = symaddr(g_attno);
    float* p_attnln = symaddr(g_attnln);
    float* p_comb   = symaddr(g_comb);
    float* p_ffh    = symaddr(g_ffh);
    float* p_ff     = symaddr(g_ff);
    float* p_feats  = symaddr(g_feats);

    // 1. embedding + positional
    embed_kernel<<<(MROWS*EE)/256, 256>>>(log_seqs, item_emb, pos_emb);

    // 2. Mamba branch
    gemm(p_seqs, EE, in_proj_w, nullptr, p_xz, MROWS, 2*DI, EE, 0);
    conv_silu_kernel<<<(MROWS*DI)/256, 256>>>(conv_w, conv_b);
    gemm(p_uconv, DI, x_proj_w, nullptr, p_xdbl, MROWS, DTR+2*NN, DI, 0);
    gemm(p_xdbl, 80, dt_proj_w, dt_proj_b, p_dt, MROWS, DI, DTR, 2);  // softplus
    scan_kernel<<<(BB*DI)/8, 256>>>(A_log, Dp);
    gemm(p_ymam, DI, out_proj_w, nullptr, p_mamba, MROWS, EE, DI, 0);

    // 3. attention branch
    gemm(p_seqs, EE, attn_in_w, attn_in_b, p_qkv, MROWS, 3*EE, EE, 0);
    attn_kernel<<<BB*HH, 512>>>();
    gemm(p_ctx, EE, attn_out_w, attn_out_b, p_attno, MROWS, EE, EE, 0);
    add_ln_kernel<<<MROWS/8, 256>>>(p_attno, p_seqs, ln1_g, ln1_b, p_attnln);

    // 4. gate + combine
    gate_kernel<<<BB, 256>>>(mw_w, mw_b);
    combine_kernel<<<(MROWS*EE)/256, 256>>>();

    // 5. FFN + LN
    gemm(p_comb, EE, ff_w1, ff_b1, p_ffh, MROWS, 4*EE, EE, 1);       // relu
    gemm(p_ffh, 4*EE, ff_w2, ff_b2, p_ff, MROWS, EE, 4*EE, 0);
    add_ln_kernel<<<MROWS/8, 256>>>(p_ff, p_comb, ln2_g, ln2_b, p_feats);

    // 6. logits
    logits_kernel<<<MROWS/8, 256>>>(pos_seqs, neg_seqs, item_emb, out);
}

// round 5
// speedup vs baseline: 2.1002x; 2.1002x over previous
#include <cuda_runtime.h>
#include <cuda_bf16.h>
#include <stdint.h>
#include <math.h>

// Problem dims
#define BB 64
#define LL 512
#define EE 256
#define HH 8
#define NN 32
#define DC 4
#define DI 512
#define DTR 16
#define MROWS (BB*LL)   // 32768

// ---------------- scratch (static device globals; no allocs) ----------------
__device__ float g_seqs  [MROWS*EE];
__device__ float g_xz    [MROWS*(2*DI)];
__device__ float g_uconv [MROWS*DI];
__device__ float g_xdbl  [MROWS*80];
__device__ float g_dt    [MROWS*DI];
__device__ float g_ymam  [MROWS*DI];
__device__ float g_mamba [MROWS*EE];
__device__ float g_qkv   [MROWS*(3*EE)];
__device__ float g_ctx   [MROWS*EE];
__device__ float g_attno [MROWS*EE];
__device__ float g_attnln[MROWS*EE];
__device__ float g_comb  [MROWS*EE];
__device__ float g_ffh   [MROWS*(4*EE)];
__device__ float g_ff    [MROWS*EE];
__device__ float g_feats [MROWS*EE];
__device__ float g_gate  [BB];

// ---------------- embedding + positional ----------------
__global__ void embed_kernel(const int* __restrict__ log_seqs,
                             const float* __restrict__ item_emb,
                             const float* __restrict__ pos_emb) {
    int i = blockIdx.x * blockDim.x + threadIdx.x;   // over MROWS*EE
    int row = i >> 8;           // b*L + l
    int e   = i & 255;
    int l   = row & (LL-1);
    int it  = __ldg(&log_seqs[row]);
    g_seqs[i] = item_emb[(size_t)it*EE + e] * 16.0f + pos_emb[l*EE + e];
}

// ---------------- TF32 helpers ----------------
__device__ __forceinline__ unsigned f2tf32(float x) {
    unsigned r;
    asm("cvt.rna.tf32.f32 %0, %1;" : "=r"(r) : "f"(x));
    return r;
}
__device__ __forceinline__ void split_tf32(float x, unsigned& hi, unsigned& lo) {
    hi = f2tf32(x);
    lo = f2tf32(x - __uint_as_float(hi));
}
__device__ __forceinline__ void mma_tf32(float c[4], const unsigned a[4], const unsigned b[2]) {
    asm volatile(
        "mma.sync.aligned.m16n8k8.row.col.f32.tf32.tf32.f32 "
        "{%0,%1,%2,%3},{%4,%5,%6,%7},{%8,%9},{%0,%1,%2,%3};"
        : "+f"(c[0]), "+f"(c[1]), "+f"(c[2]), "+f"(c[3])
        : "r"(a[0]), "r"(a[1]), "r"(a[2]), "r"(a[3]), "r"(b[0]), "r"(b[1]));
}

// ---------------- tensor-core GEMM (3xTF32): C = act(A[M,K](lda) * W[N,K]^T + bias)
// act: 0 none, 1 relu, 2 softplus. Requires M%128==0, K%8==0, N%8==0.
__global__ __launch_bounds__(256)
void gemm_tf32_kernel(const float* __restrict__ A, int lda,
                      const float* __restrict__ W,
                      const float* __restrict__ bias,
                      float* __restrict__ C,
                      int M, int N, int K, int act) {
    // smem: k-major tiles, padded stride 136 -> frag-load banks (8k+m) all distinct
    __shared__ unsigned Ah[8][136];
    __shared__ unsigned Al[8][136];
    __shared__ unsigned Bh[8][136];
    __shared__ unsigned Bl[8][136];

    int tid  = threadIdx.x;
    int lane = tid & 31;
    int wid  = tid >> 5;
    int wm = wid >> 2;          // 0..1 -> row offset wm*64
    int wn = wid & 3;           // 0..3 -> col offset wn*32
    int gid = lane >> 2;        // groupID 0..7
    int kq  = lane & 3;         // threadID_in_group 0..3

    int m0 = blockIdx.y * 128;
    int n0 = blockIdx.x * 128;

    // global-load assignment: one float4 per thread per operand
    int lr = tid >> 1;          // 0..127
    int lc = (tid & 1) * 4;     // 0 or 4
    bool wvalid = (n0 + lr) < N;

    float acc[4][4][4];
    #pragma unroll
    for (int i=0;i<4;i++)
        #pragma unroll
        for (int j=0;j<4;j++)
            #pragma unroll
            for (int r=0;r<4;r++) acc[i][j][r]=0.f;

    // prologue prefetch
    float4 a4 = *(const float4*)(A + (size_t)(m0+lr)*lda + lc);
    float4 w4 = wvalid ? *(const float4*)(W + (size_t)(n0+lr)*K + lc)
                       : make_float4(0.f,0.f,0.f,0.f);

    for (int k0 = 0; k0 < K; k0 += 8) {
        // split + store to smem
        {
            unsigned h0,l0,h1,l1,h2,l2,h3,l3;
            split_tf32(a4.x,h0,l0); split_tf32(a4.y,h1,l1);
            split_tf32(a4.z,h2,l2); split_tf32(a4.w,h3,l3);
            Ah[lc+0][lr]=h0; Al[lc+0][lr]=l0;
            Ah[lc+1][lr]=h1; Al[lc+1][lr]=l1;
            Ah[lc+2][lr]=h2; Al[lc+2][lr]=l2;
            Ah[lc+3][lr]=h3; Al[lc+3][lr]=l3;
            split_tf32(w4.x,h0,l0); split_tf32(w4.y,h1,l1);
            split_tf32(w4.z,h2,l2); split_tf32(w4.w,h3,l3);
            Bh[lc+0][lr]=h0; Bl[lc+0][lr]=l0;
            Bh[lc+1][lr]=h1; Bl[lc+1][lr]=l1;
            Bh[lc+2][lr]=h2; Bl[lc+2][lr]=l2;
            Bh[lc+3][lr]=h3; Bl[lc+3][lr]=l3;
        }
        __syncthreads();

        // prefetch next tile (overlaps with compute below)
        if (k0 + 8 < K) {
            a4 = *(const float4*)(A + (size_t)(m0+lr)*lda + k0 + 8 + lc);
            w4 = wvalid ? *(const float4*)(W + (size_t)(n0+lr)*K + k0 + 8 + lc)
                        : make_float4(0.f,0.f,0.f,0.f);
        }

        // load fragments
        unsigned fah[4][4], fal[4][4], fb[4][2];
        #pragma unroll
        for (int mi=0; mi<4; mi++) {
            int rb = wm*64 + mi*16;
            fah[mi][0] = Ah[kq  ][rb+gid];
            fah[mi][1] = Ah[kq  ][rb+8+gid];
            fah[mi][2] = Ah[kq+4][rb+gid];
            fah[mi][3] = Ah[kq+4][rb+8+gid];
            fal[mi][0] = Al[kq  ][rb+gid];
            fal[mi][1] = Al[kq  ][rb+8+gid];
            fal[mi][2] = Al[kq+4][rb+gid];
            fal[mi][3] = Al[kq+4][rb+8+gid];
        }
        #pragma unroll
        for (int ni=0; ni<4; ni++) {
            int nb = wn*32 + ni*8;
            fb[ni][0] = Bh[kq  ][nb+gid];
            fb[ni][1] = Bh[kq+4][nb+gid];
        }
        // pass 1: Ahi*Bhi, pass 2: Alo*Bhi
        #pragma unroll
        for (int mi=0; mi<4; mi++)
            #pragma unroll
            for (int ni=0; ni<4; ni++) {
                mma_tf32(acc[mi][ni], fah[mi], fb[ni]);
                mma_tf32(acc[mi][ni], fal[mi], fb[ni]);
            }
        // pass 3: Ahi*Blo (reuse fb regs)
        #pragma unroll
        for (int ni=0; ni<4; ni++) {
            int nb = wn*32 + ni*8;
            fb[ni][0] = Bl[kq  ][nb+gid];
            fb[ni][1] = Bl[kq+4][nb+gid];
        }
        #pragma unroll
        for (int mi=0; mi<4; mi++)
            #pragma unroll
            for (int ni=0; ni<4; ni++)
                mma_tf32(acc[mi][ni], fah[mi], fb[ni]);
        __syncthreads();
    }

    // epilogue: c0 (r,c) c1 (r,c+1) c2 (r+8,c) c3 (r+8,c+1); N%8==0 so pair guard = c<N
    #pragma unroll
    for (int mi=0; mi<4; mi++) {
        int r = m0 + wm*64 + mi*16 + gid;
        #pragma unroll
        for (int ni=0; ni<4; ni++) {
            int c = n0 + wn*32 + ni*8 + kq*2;
            if (c < N) {
                float v0 = acc[mi][ni][0], v1 = acc[mi][ni][1];
                float v2 = acc[mi][ni][2], v3 = acc[mi][ni][3];
                if (bias) {
                    float b0 = bias[c], b1 = bias[c+1];
                    v0 += b0; v1 += b1; v2 += b0; v3 += b1;
                }
                if (act == 1) {
                    v0=fmaxf(v0,0.f); v1=fmaxf(v1,0.f); v2=fmaxf(v2,0.f); v3=fmaxf(v3,0.f);
                } else if (act == 2) {
                    v0 = (v0>20.f)?v0:log1pf(__expf(v0));
                    v1 = (v1>20.f)?v1:log1pf(__expf(v1));
                    v2 = (v2>20.f)?v2:log1pf(__expf(v2));
                    v3 = (v3>20.f)?v3:log1pf(__expf(v3));
                }
                *(float2*)(C + (size_t)r*N + c)       = make_float2(v0, v1);
                *(float2*)(C + (size_t)(r+8)*N + c)   = make_float2(v2, v3);
            }
        }
    }
}

// ---------------- causal depthwise conv (DC=4) + SiLU ----------------
__global__ void conv_silu_kernel(const float* __restrict__ conv_w,
                                 const float* __restrict__ conv_b) {
    int i = blockIdx.x * blockDim.x + threadIdx.x;   // over MROWS*DI
    int row = i >> 9;           // b*L+l
    int d   = i & (DI-1);
    int b   = row >> 9;
    int l   = row & (LL-1);
    float acc = conv_b[d];
    #pragma unroll
    for (int k=0;k<DC;k++) {
        int ll = l - (DC-1) + k;
        if (ll >= 0)
            acc = fmaf(g_xz[(size_t)((b<<9)+ll)*(2*DI) + d], conv_w[d*DC + k], acc);
    }
    float s = acc / (1.f + __expf(-acc));   // silu
    g_uconv[i] = s;
}

// ---------------- selective scan v2: thread per (b,d), h[32] in regs ----------------
// Exploits A_n = -(n+1) (verified at runtime): exp(dt*A_n) = p^(n+1), p = exp(-dt).
#define TCH 16
__global__ __launch_bounds__(128)
void scan2_kernel(const float* __restrict__ A_log,
                  const float* __restrict__ Dp) {
    __shared__ float sBC[TCH][64];      // [t][0..31]=B, [t][32..63]=C
    int b = blockIdx.x >> 2;
    int q = blockIdx.x & 3;
    int d = q*128 + threadIdx.x;
    int brow = b << 9;

    float h[32];
    #pragma unroll
    for (int n=0;n<32;n++) h[n]=0.f;
    float dpv = Dp[d];

    bool fast = true;
    #pragma unroll
    for (int n=0;n<32;n++) {
        float a = -__expf(A_log[d*NN + n]);
        if (fabsf(a + (float)(n+1)) > 1e-3f*(float)(n+1)) fast = false;
    }

    for (int t0=0; t0<LL; t0+=TCH) {
        __syncthreads();
        #pragma unroll
        for (int it=0; it<2; it++) {
            int p  = it*128 + threadIdx.x;   // float4 index 0..255
            int t  = p >> 4;
            int j  = (p & 15) * 4;
            *(float4*)&sBC[t][j] =
                *(const float4*)&g_xdbl[(size_t)(brow+t0+t)*80 + DTR + j];
        }
        __syncthreads();

        if (fast) {
            #pragma unroll 4
            for (int tt=0; tt<TCH; tt++) {
                int row = brow + t0 + tt;
                float dtv = g_dt   [(size_t)row*DI + d];
                float uv  = g_uconv[(size_t)row*DI + d];
                float p  = __expf(-dtv);
                float du = dtv * uv;
                float w  = 1.f;
                float y0=0.f,y1=0.f,y2=0.f,y3=0.f;
                #pragma unroll
                for (int n=0;n<32;n+=4) {
                    w *= p; h[n  ]=fmaf(w,h[n  ],du*sBC[tt][n  ]); y0=fmaf(h[n  ],sBC[tt][32+n  ],y0);
                    w *= p; h[n+1]=fmaf(w,h[n+1],du*sBC[tt][n+1]); y1=fmaf(h[n+1],sBC[tt][33+n  ],y1);
                    w *= p; h[n+2]=fmaf(w,h[n+2],du*sBC[tt][n+2]); y2=fmaf(h[n+2],sBC[tt][34+n  ],y2);
                    w *= p; h[n+3]=fmaf(w,h[n+3],du*sBC[tt][n+3]); y3=fmaf(h[n+3],sBC[tt][35+n  ],y3);
                }
                float y = (y0+y1)+(y2+y3);
                float z  = g_xz[(size_t)row*(2*DI) + DI + d];
                float sz = z / (1.f + __expf(-z));
                g_ymam[(size_t)row*DI + d] = (y + uv*dpv) * sz;
            }
        } else {
            // exact fallback (not expected to run on this dataset)
            for (int tt=0; tt<TCH; tt++) {
                int row = brow + t0 + tt;
                float dtv = g_dt   [(size_t)row*DI + d];
                float uv  = g_uconv[(size_t)row*DI + d];
                float du = dtv * uv;
                float y = 0.f;
                #pragma unroll
                for (int n=0;n<32;n++) {
                    float a = -__expf(A_log[d*NN + n]);
                    float e = __expf(dtv * a);
                    h[n] = fmaf(e, h[n], du*sBC[tt][n]);
                    y = fmaf(h[n], sBC[tt][32+n], y);
                }
                float z  = g_xz[(size_t)row*(2*DI) + DI + d];
                float sz = z / (1.f + __expf(-z));
                g_ymam[(size_t)row*DI + d] = (y + uv*dpv) * sz;
            }
        }
    }
}

// ---------------- fused attention: block = (b,h), thread = query ----------------
__global__ __launch_bounds__(512)
void attn_kernel() {
    int b = blockIdx.x / HH, h = blockIdx.x % HH;
    __shared__ float Ks[64][32];
    __shared__ float Vs[64][32];
    int q = threadIdx.x;
    const float scale = 0.17677669529663687f;   // 1/sqrt(32)
    int rowq = (b<<9) + q;
    float qreg[32];
    {
        const float4* qp = (const float4*)(g_qkv + (size_t)rowq*(3*EE) + h*32);
        #pragma unroll
        for (int i=0;i<8;i++) {
            float4 v = qp[i];
            qreg[i*4+0]=v.x*scale; qreg[i*4+1]=v.y*scale;
            qreg[i*4+2]=v.z*scale; qreg[i*4+3]=v.w*scale;
        }
    }
    float m = -1e30f, lsum = 0.f;
    float o[32];
    #pragma unroll
    for (int i=0;i<32;i++) o[i]=0.f;

    for (int t=0; t<LL; t+=64) {
        __syncthreads();
        {
            int idx = threadIdx.x;
            int r = idx >> 3, c = (idx & 7) * 4;
            int rowk = (b<<9) + t + r;
            *(float4*)&Ks[r][c] = *(const float4*)(g_qkv + (size_t)rowk*(3*EE) + EE   + h*32 + c);
            *(float4*)&Vs[r][c] = *(const float4*)(g_qkv + (size_t)rowk*(3*EE) + 2*EE + h*32 + c);
        }
        __syncthreads();
        for (int j=0;j<64;j++) {
            float s = 0.f;
            const float4* kr = (const float4*)Ks[j];
            #pragma unroll
            for (int i=0;i<8;i++) {
                float4 k4 = kr[i];
                s = fmaf(qreg[i*4+0], k4.x, s); s = fmaf(qreg[i*4+1], k4.y, s);
                s = fmaf(qreg[i*4+2], k4.z, s); s = fmaf(qreg[i*4+3], k4.w, s);
            }
            if (s > m) {
                float corr = __expf(m - s);
                m = s;
                lsum *= corr;
                #pragma unroll
                for (int i=0;i<32;i++) o[i] *= corr;
            }
            float p = __expf(s - m);
            lsum += p;
            const float4* vr = (const float4*)Vs[j];
            #pragma unroll
            for (int i=0;i<8;i++) {
                float4 v4 = vr[i];
                o[i*4+0] = fmaf(p, v4.x, o[i*4+0]);
                o[i*4+1] = fmaf(p, v4.y, o[i*4+1]);
                o[i*4+2] = fmaf(p, v4.z, o[i*4+2]);
                o[i*4+3] = fmaf(p, v4.w, o[i*4+3]);
            }
        }
    }
    float inv = 1.f / lsum;
    float4* op = (float4*)(g_ctx + (size_t)rowq*EE + h*32);
    #pragma unroll
    for (int i=0;i<8;i++)
        op[i] = make_float4(o[i*4]*inv, o[i*4+1]*inv, o[i*4+2]*inv, o[i*4+3]*inv);
}

// ---------------- residual add + LayerNorm (warp per row, E=256) ----------------
__global__ void add_ln_kernel(const float* __restrict__ x, const float* __restrict__ res,
                              const float* __restrict__ g, const float* __restrict__ bta,
                              float* __restrict__ out) {
    int row  = blockIdx.x * (blockDim.x >> 5) + (threadIdx.x >> 5);
    int lane = threadIdx.x & 31;
    const float4* xp = (const float4*)(x   + (size_t)row*EE);
    const float4* rp = (const float4*)(res + (size_t)row*EE);
    float v[8];
    float4 a0 = xp[lane],     b0 = rp[lane];
    float4 a1 = xp[lane+32],  b1 = rp[lane+32];
    v[0]=a0.x+b0.x; v[1]=a0.y+b0.y; v[2]=a0.z+b0.z; v[3]=a0.w+b0.w;
    v[4]=a1.x+b1.x; v[5]=a1.y+b1.y; v[6]=a1.z+b1.z; v[7]=a1.w+b1.w;
    float s=0.f, s2=0.f;
    #pragma unroll
    for (int i=0;i<8;i++){ s += v[i]; s2 = fmaf(v[i], v[i], s2); }
    #pragma unroll
    for (int off=16; off; off>>=1) {
        s  += __shfl_xor_sync(0xffffffffu, s,  off);
        s2 += __shfl_xor_sync(0xffffffffu, s2, off);
    }
    float mean = s * (1.f/EE);
    float var  = s2 * (1.f/EE) - mean*mean;
    float rstd = rsqrtf(var + 1e-6f);
    float4* op = (float4*)(out + (size_t)row*EE);
    const float4* gp = (const float4*)g;
    const float4* bp = (const float4*)bta;
    float4 g0=gp[lane], g1=gp[lane+32], c0=bp[lane], c1=bp[lane+32];
    op[lane]    = make_float4((v[0]-mean)*rstd*g0.x+c0.x, (v[1]-mean)*rstd*g0.y+c0.y,
                              (v[2]-mean)*rstd*g0.z+c0.z, (v[3]-mean)*rstd*g0.w+c0.w);
    op[lane+32] = make_float4((v[4]-mean)*rstd*g1.x+c1.x, (v[5]-mean)*rstd*g1.y+c1.y,
                              (v[6]-mean)*rstd*g1.z+c1.z, (v[7]-mean)*rstd*g1.w+c1.w);
}

// ---------------- gate: sigmoid(mean_l(seqs) @ mw_w^T + mw_b) per batch ----------------
__global__ void gate_kernel(const float* __restrict__ mw_w, const float* __restrict__ mw_b) {
    int b = blockIdx.x;
    int e = threadIdx.x;           // 256 threads
    float s = 0.f;
    for (int l=0;l<LL;l++) s += g_seqs[(size_t)((b<<9)+l)*EE + e];
    s = (s * (1.f/LL)) * mw_w[e];
    __shared__ float red[256];
    red[e] = s; __syncthreads();
    for (int st=128; st; st>>=1) { if (e < st) red[e] += red[e+st]; __syncthreads(); }
    if (e == 0) g_gate[b] = 1.f / (1.f + __expf(-(red[0] + mw_b[0])));
}

// ---------------- gated combine ----------------
__global__ void combine_kernel() {
    int i = blockIdx.x * blockDim.x + threadIdx.x;   // over MROWS*EE
    int row = i >> 8;
    float w = g_gate[row >> 9];
    g_comb[i] = w * g_mamba[i] + (1.f - w) * g_attnln[i];
}

// ---------------- logits: warp per (b,l), pos & neg dots ----------------
__global__ void logits_kernel(const int* __restrict__ pos, const int* __restrict__ neg,
                              const float* __restrict__ item_emb, float* __restrict__ out) {
    int row  = blockIdx.x * (blockDim.x >> 5) + (threadIdx.x >> 5);
    int lane = threadIdx.x & 31;
    const float4* f = (const float4*)(g_feats + (size_t)row*EE);
    float4 f0 = f[lane], f1 = f[lane+32];
    int pi = __ldg(&pos[row]), ni = __ldg(&neg[row]);
    const float4* pe = (const float4*)(item_emb + (size_t)pi*EE);
    const float4* ne = (const float4*)(item_emb + (size_t)ni*EE);
    float4 p0 = pe[lane], p1 = pe[lane+32];
    float4 n0 = ne[lane], n1 = ne[lane+32];
    float dp = f0.x*p0.x+f0.y*p0.y+f0.z*p0.z+f0.w*p0.w
             + f1.x*p1.x+f1.y*p1.y+f1.z*p1.z+f1.w*p1.w;
    float dn = f0.x*n0.x+f0.y*n0.y+f0.z*n0.z+f0.w*n0.w
             + f1.x*n1.x+f1.y*n1.y+f1.z*n1.z+f1.w*n1.w;
    #pragma unroll
    for (int off=16; off; off>>=1) {
        dp += __shfl_xor_sync(0xffffffffu, dp, off);
        dn += __shfl_xor_sync(0xffffffffu, dn, off);
    }
    if (lane == 0) {
        out[row]         = dp;
        out[MROWS + row] = dn;
    }
}

// ---------------- host ----------------
static float* symaddr(const void* sym) {
    void* p = nullptr;
    cudaGetSymbolAddress(&p, sym);
    return (float*)p;
}

static void gemm(const float* A, int lda, const float* W, const float* bias,
                 float* C, int M, int N, int K, int act) {
    dim3 grid((N + 127) / 128, M / 128);
    gemm_tf32_kernel<<<grid, 256>>>(A, lda, W, bias, C, M, N, K, act);
}

extern "C" void kernel_launch(void* const* d_in, const int* in_sizes, int n_in,
                              void* d_out, int out_size) {
    const int*   log_seqs  = (const int*)  d_in[1];
    const int*   pos_seqs  = (const int*)  d_in[2];
    const int*   neg_seqs  = (const int*)  d_in[3];
    const float* item_emb  = (const float*)d_in[4];
    const float* pos_emb   = (const float*)d_in[5];
    const float* in_proj_w = (const float*)d_in[6];
    const float* conv_w    = (const float*)d_in[7];
    const float* conv_b    = (const float*)d_in[8];
    const float* x_proj_w  = (const float*)d_in[9];
    const float* dt_proj_w = (const float*)d_in[10];
    const float* dt_proj_b = (const float*)d_in[11];
    const float* A_log     = (const float*)d_in[12];
    const float* Dp        = (const float*)d_in[13];
    const float* out_proj_w= (const float*)d_in[14];
    const float* attn_in_w = (const float*)d_in[15];
    const float* attn_in_b = (const float*)d_in[16];
    const float* attn_out_w= (const float*)d_in[17];
    const float* attn_out_b= (const float*)d_in[18];
    const float* ln1_g     = (const float*)d_in[19];
    const float* ln1_b     = (const float*)d_in[20];
    const float* mw_w      = (const float*)d_in[21];
    const float* mw_b      = (const float*)d_in[22];
    const float* ff_w1     = (const float*)d_in[23];
    const float* ff_b1     = (const float*)d_in[24];
    const float* ff_w2     = (const float*)d_in[25];
    const float* ff_b2     = (const float*)d_in[26];
    const float* ln2_g     = (const float*)d_in[27];
    const float* ln2_b     = (const float*)d_in[28];
    float* out = (float*)d_out;

    float* p_seqs   = symaddr(g_seqs);
    float* p_xz     = symaddr(g_xz);
    float* p_uconv  = symaddr(g_uconv);
    float* p_xdbl   = symaddr(g_xdbl);
    float* p_dt     = symaddr(g_dt);
    float* p_ymam   = symaddr(g_ymam);
    float* p_mamba  = symaddr(g_mamba);
    float* p_qkv    = symaddr(g_qkv);
    float* p_ctx    = symaddr(g_ctx);
    float* p_attno  = symaddr(g_attno);
    float* p_attnln = symaddr(g_attnln);
    float* p_comb   = symaddr(g_comb);
    float* p_ffh    = symaddr(g_ffh);
    float* p_ff     = symaddr(g_ff);
    float* p_feats  = symaddr(g_feats);

    // 1. embedding + positional
    embed_kernel<<<(MROWS*EE)/256, 256>>>(log_seqs, item_emb, pos_emb);

    // 2. Mamba branch
    gemm(p_seqs, EE, in_proj_w, nullptr, p_xz, MROWS, 2*DI, EE, 0);
    conv_silu_kernel<<<(MROWS*DI)/256, 256>>>(conv_w, conv_b);
    gemm(p_uconv, DI, x_proj_w, nullptr, p_xdbl, MROWS, DTR+2*NN, DI, 0);
    gemm(p_xdbl, 80, dt_proj_w, dt_proj_b, p_dt, MROWS, DI, DTR, 2);  // softplus
    scan2_kernel<<<BB*4, 128>>>(A_log, Dp);
    gemm(p_ymam, DI, out_proj_w, nullptr, p_mamba, MROWS, EE, DI, 0);

    // 3. attention branch
    gemm(p_seqs, EE, attn_in_w, attn_in_b, p_qkv, MROWS, 3*EE, EE, 0);
    attn_kernel<<<BB*HH, 512>>>();
    gemm(p_ctx, EE, attn_out_w, attn_out_b, p_attno, MROWS, EE, EE, 0);
    add_ln_kernel<<<MROWS/8, 256>>>(p_attno, p_seqs, ln1_g, ln1_b, p_attnln);

    // 4. gate + combine
    gate_kernel<<<BB, 256>>>(mw_w, mw_b);
    combine_kernel<<<(MROWS*EE)/256, 256>>>();

    // 5. FFN + LN
    gemm(p_comb, EE, ff_w1, ff_b1, p_ffh, MROWS, 4*EE, EE, 1);       // relu
    gemm(p_ffh, 4*EE, ff_w2, ff_b2, p_ff, MROWS, EE, 4*EE, 0);
    add_ln_kernel<<<MROWS/8, 256>>>(p_ff, p_comb, ln2_g, ln2_b, p_feats);

    // 6. logits
    logits_kernel<<<MROWS/8, 256>>>(pos_seqs, neg_seqs, item_emb, out);
}

// round 6
// speedup vs baseline: 2.1174x; 1.0082x over previous
#include <cuda_runtime.h>
#include <cuda_bf16.h>
#include <stdint.h>
#include <math.h>

// Problem dims
#define BB 64
#define LL 512
#define EE 256
#define HH 8
#define NN 32
#define DC 4
#define DI 512
#define DTR 16
#define MROWS (BB*LL)   // 32768

// ---------------- scratch (static device globals; no allocs) ----------------
__device__ float g_seqs  [MROWS*EE];
__device__ float g_xz    [MROWS*(2*DI)];
__device__ float g_uconv [MROWS*DI];
__device__ float g_xdbl  [MROWS*80];
__device__ float g_dt    [MROWS*DI];
__device__ float g_ymam  [MROWS*DI];
__device__ float g_mamba [MROWS*EE];
__device__ float g_qkv   [MROWS*(3*EE)];
__device__ float g_ctx   [MROWS*EE];
__device__ float g_attno [MROWS*EE];
__device__ float g_attnln[MROWS*EE];
__device__ float g_comb  [MROWS*EE];
__device__ float g_ffh   [MROWS*(4*EE)];
__device__ float g_ff    [MROWS*EE];
__device__ float g_feats [MROWS*EE];
__device__ float g_gate  [BB];

// ---------------- embedding + positional ----------------
__global__ void embed_kernel(const int* __restrict__ log_seqs,
                             const float* __restrict__ item_emb,
                             const float* __restrict__ pos_emb) {
    int i = blockIdx.x * blockDim.x + threadIdx.x;   // over MROWS*EE
    int row = i >> 8;           // b*L + l
    int e   = i & 255;
    int l   = row & (LL-1);
    int it  = __ldg(&log_seqs[row]);
    g_seqs[i] = item_emb[(size_t)it*EE + e] * 16.0f + pos_emb[l*EE + e];
}

// ---------------- TF32 helpers ----------------
__device__ __forceinline__ unsigned f2tf32(float x) {
    unsigned r;
    asm("cvt.rna.tf32.f32 %0, %1;" : "=r"(r) : "f"(x));
    return r;
}
__device__ __forceinline__ void split_tf32(float x, unsigned& hi, unsigned& lo) {
    hi = f2tf32(x);
    lo = f2tf32(x - __uint_as_float(hi));
}
__device__ __forceinline__ void mma_tf32(float c[4], const unsigned a[4], const unsigned b[2]) {
    asm volatile(
        "mma.sync.aligned.m16n8k8.row.col.f32.tf32.tf32.f32 "
        "{%0,%1,%2,%3},{%4,%5,%6,%7},{%8,%9},{%0,%1,%2,%3};"
        : "+f"(c[0]), "+f"(c[1]), "+f"(c[2]), "+f"(c[3])
        : "r"(a[0]), "r"(a[1]), "r"(a[2]), "r"(a[3]), "r"(b[0]), "r"(b[1]));
}

// ---------------- tensor-core GEMM (3xTF32, double-buffered):
// C = act(A[M,K](lda) * W[N,K]^T + bias)
// act: 0 none, 1 relu, 2 softplus. Requires M%128==0, K%8==0, N%8==0.
__global__ __launch_bounds__(256)
void gemm_tf32_kernel(const float* __restrict__ A, int lda,
                      const float* __restrict__ W,
                      const float* __restrict__ bias,
                      float* __restrict__ C,
                      int M, int N, int K, int act) {
    // two stages; k-major tiles, padded stride 136 -> conflict-free frag loads
    __shared__ unsigned Ah[2][8][136];
    __shared__ unsigned Al[2][8][136];
    __shared__ unsigned Bh[2][8][136];
    __shared__ unsigned Bl[2][8][136];

    int tid  = threadIdx.x;
    int lane = tid & 31;
    int wid  = tid >> 5;
    int wm = wid >> 2;          // 0..1 -> row offset wm*64
    int wn = wid & 3;           // 0..3 -> col offset wn*32
    int gid = lane >> 2;        // groupID 0..7
    int kq  = lane & 3;         // threadID_in_group 0..3

    int m0 = blockIdx.y * 128;
    int n0 = blockIdx.x * 128;

    // global-load assignment: one float4 per thread per operand
    int lr = tid >> 1;          // 0..127
    int lc = (tid & 1) * 4;     // 0 or 4
    bool wvalid = (n0 + lr) < N;

    float acc[4][4][4];
    #pragma unroll
    for (int i=0;i<4;i++)
        #pragma unroll
        for (int j=0;j<4;j++)
            #pragma unroll
            for (int r=0;r<4;r++) acc[i][j][r]=0.f;

    const float* aptr = A + (size_t)(m0+lr)*lda + lc;
    const float* wptr = W + (size_t)(n0+lr)*K + lc;

    // prologue: load + split + store stage 0
    float4 a4 = *(const float4*)aptr;
    float4 w4 = wvalid ? *(const float4*)wptr : make_float4(0.f,0.f,0.f,0.f);
    {
        unsigned h0,l0,h1,l1,h2,l2,h3,l3;
        split_tf32(a4.x,h0,l0); split_tf32(a4.y,h1,l1);
        split_tf32(a4.z,h2,l2); split_tf32(a4.w,h3,l3);
        Ah[0][lc+0][lr]=h0; Al[0][lc+0][lr]=l0;
        Ah[0][lc+1][lr]=h1; Al[0][lc+1][lr]=l1;
        Ah[0][lc+2][lr]=h2; Al[0][lc+2][lr]=l2;
        Ah[0][lc+3][lr]=h3; Al[0][lc+3][lr]=l3;
        split_tf32(w4.x,h0,l0); split_tf32(w4.y,h1,l1);
        split_tf32(w4.z,h2,l2); split_tf32(w4.w,h3,l3);
        Bh[0][lc+0][lr]=h0; Bl[0][lc+0][lr]=l0;
        Bh[0][lc+1][lr]=h1; Bl[0][lc+1][lr]=l1;
        Bh[0][lc+2][lr]=h2; Bl[0][lc+2][lr]=l2;
        Bh[0][lc+3][lr]=h3; Bl[0][lc+3][lr]=l3;
    }
    __syncthreads();

    int nIter = K >> 3;
    for (int it = 0; it < nIter; it++) {
        int s = it & 1;
        bool more = (it + 1) < nIter;

        // prefetch next global tile (latency hidden under MMAs below)
        if (more) {
            int ko = (it+1) << 3;
            a4 = *(const float4*)(aptr + ko);
            w4 = wvalid ? *(const float4*)(wptr + ko) : make_float4(0.f,0.f,0.f,0.f);
        }

        // load fragments from stage s
        unsigned fah[4][4], fal[4][4], fb[4][2];
        #pragma unroll
        for (int mi=0; mi<4; mi++) {
            int rb = wm*64 + mi*16;
            fah[mi][0] = Ah[s][kq  ][rb+gid];
            fah[mi][1] = Ah[s][kq  ][rb+8+gid];
            fah[mi][2] = Ah[s][kq+4][rb+gid];
            fah[mi][3] = Ah[s][kq+4][rb+8+gid];
            fal[mi][0] = Al[s][kq  ][rb+gid];
            fal[mi][1] = Al[s][kq  ][rb+8+gid];
            fal[mi][2] = Al[s][kq+4][rb+gid];
            fal[mi][3] = Al[s][kq+4][rb+8+gid];
        }
        #pragma unroll
        for (int ni=0; ni<4; ni++) {
            int nb = wn*32 + ni*8;
            fb[ni][0] = Bh[s][kq  ][nb+gid];
            fb[ni][1] = Bh[s][kq+4][nb+gid];
        }
        // pass 1: Ahi*Bhi, pass 2: Alo*Bhi
        #pragma unroll
        for (int mi=0; mi<4; mi++)
            #pragma unroll
            for (int ni=0; ni<4; ni++) {
                mma_tf32(acc[mi][ni], fah[mi], fb[ni]);
                mma_tf32(acc[mi][ni], fal[mi], fb[ni]);
            }
        // pass 3: Ahi*Blo
        #pragma unroll
        for (int ni=0; ni<4; ni++) {
            int nb = wn*32 + ni*8;
            fb[ni][0] = Bl[s][kq  ][nb+gid];
            fb[ni][1] = Bl[s][kq+4][nb+gid];
        }
        #pragma unroll
        for (int mi=0; mi<4; mi++)
            #pragma unroll
            for (int ni=0; ni<4; ni++)
                mma_tf32(acc[mi][ni], fah[mi], fb[ni]);

        // split + store next tile into stage s^1 (overlaps MMA pipeline drain)
        if (more) {
            int d = s ^ 1;
            unsigned h0,l0,h1,l1,h2,l2,h3,l3;
            split_tf32(a4.x,h0,l0); split_tf32(a4.y,h1,l1);
            split_tf32(a4.z,h2,l2); split_tf32(a4.w,h3,l3);
            Ah[d][lc+0][lr]=h0; Al[d][lc+0][lr]=l0;
            Ah[d][lc+1][lr]=h1; Al[d][lc+1][lr]=l1;
            Ah[d][lc+2][lr]=h2; Al[d][lc+2][lr]=l2;
            Ah[d][lc+3][lr]=h3; Al[d][lc+3][lr]=l3;
            split_tf32(w4.x,h0,l0); split_tf32(w4.y,h1,l1);
            split_tf32(w4.z,h2,l2); split_tf32(w4.w,h3,l3);
            Bh[d][lc+0][lr]=h0; Bl[d][lc+0][lr]=l0;
            Bh[d][lc+1][lr]=h1; Bl[d][lc+1][lr]=l1;
            Bh[d][lc+2][lr]=h2; Bl[d][lc+2][lr]=l2;
            Bh[d][lc+3][lr]=h3; Bl[d][lc+3][lr]=l3;
        }
        __syncthreads();
    }

    // epilogue: c0 (r,c) c1 (r,c+1) c2 (r+8,c) c3 (r+8,c+1); N%8==0 so pair guard = c<N
    #pragma unroll
    for (int mi=0; mi<4; mi++) {
        int r = m0 + wm*64 + mi*16 + gid;
        #pragma unroll
        for (int ni=0; ni<4; ni++) {
            int c = n0 + wn*32 + ni*8 + kq*2;
            if (c < N) {
                float v0 = acc[mi][ni][0], v1 = acc[mi][ni][1];
                float v2 = acc[mi][ni][2], v3 = acc[mi][ni][3];
                if (bias) {
                    float b0 = bias[c], b1 = bias[c+1];
                    v0 += b0; v1 += b1; v2 += b0; v3 += b1;
                }
                if (act == 1) {
                    v0=fmaxf(v0,0.f); v1=fmaxf(v1,0.f); v2=fmaxf(v2,0.f); v3=fmaxf(v3,0.f);
                } else if (act == 2) {
                    v0 = (v0>20.f)?v0:log1pf(__expf(v0));
                    v1 = (v1>20.f)?v1:log1pf(__expf(v1));
                    v2 = (v2>20.f)?v2:log1pf(__expf(v2));
                    v3 = (v3>20.f)?v3:log1pf(__expf(v3));
                }
                *(float2*)(C + (size_t)r*N + c)       = make_float2(v0, v1);
                *(float2*)(C + (size_t)(r+8)*N + c)   = make_float2(v2, v3);
            }
        }
    }
}

// ---------------- causal depthwise conv (DC=4) + SiLU ----------------
__global__ void conv_silu_kernel(const float* __restrict__ conv_w,
                                 const float* __restrict__ conv_b) {
    int i = blockIdx.x * blockDim.x + threadIdx.x;   // over MROWS*DI
    int row = i >> 9;           // b*L+l
    int d   = i & (DI-1);
    int b   = row >> 9;
    int l   = row & (LL-1);
    float acc = conv_b[d];
    #pragma unroll
    for (int k=0;k<DC;k++) {
        int ll = l - (DC-1) + k;
        if (ll >= 0)
            acc = fmaf(g_xz[(size_t)((b<<9)+ll)*(2*DI) + d], conv_w[d*DC + k], acc);
    }
    float s = acc / (1.f + __expf(-acc));   // silu
    g_uconv[i] = s;
}

// ---------------- selective scan v2: thread per (b,d), h[32] in regs ----------------
// Exploits A_n = -(n+1) (verified at runtime): exp(dt*A_n) = p^(n+1), p = exp(-dt).
#define TCH 16
__global__ __launch_bounds__(128)
void scan2_kernel(const float* __restrict__ A_log,
                  const float* __restrict__ Dp) {
    __shared__ float sBC[TCH][64];      // [t][0..31]=B, [t][32..63]=C
    int b = blockIdx.x >> 2;
    int q = blockIdx.x & 3;
    int d = q*128 + threadIdx.x;
    int brow = b << 9;

    float h[32];
    #pragma unroll
    for (int n=0;n<32;n++) h[n]=0.f;
    float dpv = Dp[d];

    bool fast = true;
    #pragma unroll
    for (int n=0;n<32;n++) {
        float a = -__expf(A_log[d*NN + n]);
        if (fabsf(a + (float)(n+1)) > 1e-3f*(float)(n+1)) fast = false;
    }

    for (int t0=0; t0<LL; t0+=TCH) {
        __syncthreads();
        #pragma unroll
        for (int it=0; it<2; it++) {
            int p  = it*128 + threadIdx.x;   // float4 index 0..255
            int t  = p >> 4;
            int j  = (p & 15) * 4;
            *(float4*)&sBC[t][j] =
                *(const float4*)&g_xdbl[(size_t)(brow+t0+t)*80 + DTR + j];
        }
        __syncthreads();

        if (fast) {
            #pragma unroll 4
            for (int tt=0; tt<TCH; tt++) {
                int row = brow + t0 + tt;
                float dtv = g_dt   [(size_t)row*DI + d];
                float uv  = g_uconv[(size_t)row*DI + d];
                float p  = __expf(-dtv);
                float du = dtv * uv;
                float w  = 1.f;
                float y0=0.f,y1=0.f,y2=0.f,y3=0.f;
                #pragma unroll
                for (int n=0;n<32;n+=4) {
                    w *= p; h[n  ]=fmaf(w,h[n  ],du*sBC[tt][n  ]); y0=fmaf(h[n  ],sBC[tt][32+n  ],y0);
                    w *= p; h[n+1]=fmaf(w,h[n+1],du*sBC[tt][n+1]); y1=fmaf(h[n+1],sBC[tt][33+n  ],y1);
                    w *= p; h[n+2]=fmaf(w,h[n+2],du*sBC[tt][n+2]); y2=fmaf(h[n+2],sBC[tt][34+n  ],y2);
                    w *= p; h[n+3]=fmaf(w,h[n+3],du*sBC[tt][n+3]); y3=fmaf(h[n+3],sBC[tt][35+n  ],y3);
                }
                float y = (y0+y1)+(y2+y3);
                float z  = g_xz[(size_t)row*(2*DI) + DI + d];
                float sz = z / (1.f + __expf(-z));
                g_ymam[(size_t)row*DI + d] = (y + uv*dpv) * sz;
            }
        } else {
            // exact fallback (not expected to run on this dataset)
            for (int tt=0; tt<TCH; tt++) {
                int row = brow + t0 + tt;
                float dtv = g_dt   [(size_t)row*DI + d];
                float uv  = g_uconv[(size_t)row*DI + d];
                float du = dtv * uv;
                float y = 0.f;
                #pragma unroll
                for (int n=0;n<32;n++) {
                    float a = -__expf(A_log[d*NN + n]);
                    float e = __expf(dtv * a);
                    h[n] = fmaf(e, h[n], du*sBC[tt][n]);
                    y = fmaf(h[n], sBC[tt][32+n], y);
                }
                float z  = g_xz[(size_t)row*(2*DI) + DI + d];
                float sz = z / (1.f + __expf(-z));
                g_ymam[(size_t)row*DI + d] = (y + uv*dpv) * sz;
            }
        }
    }
}

// ---------------- fused attention: block = (b,h), thread = query ----------------
__global__ __launch_bounds__(512)
void attn_kernel() {
    int b = blockIdx.x / HH, h = blockIdx.x % HH;
    __shared__ float Ks[64][32];
    __shared__ float Vs[64][32];
    int q = threadIdx.x;
    const float scale = 0.17677669529663687f;   // 1/sqrt(32)
    int rowq = (b<<9) + q;
    float qreg[32];
    {
        const float4* qp = (const float4*)(g_qkv + (size_t)rowq*(3*EE) + h*32);
        #pragma unroll
        for (int i=0;i<8;i++) {
            float4 v = qp[i];
            qreg[i*4+0]=v.x*scale; qreg[i*4+1]=v.y*scale;
            qreg[i*4+2]=v.z*scale; qreg[i*4+3]=v.w*scale;
        }
    }
    float m = -1e30f, lsum = 0.f;
    float o[32];
    #pragma unroll
    for (int i=0;i<32;i++) o[i]=0.f;

    for (int t=0; t<LL; t+=64) {
        __syncthreads();
        {
            int idx = threadIdx.x;
            int r = idx >> 3, c = (idx & 7) * 4;
            int rowk = (b<<9) + t + r;
            *(float4*)&Ks[r][c] = *(const float4*)(g_qkv + (size_t)rowk*(3*EE) + EE   + h*32 + c);
            *(float4*)&Vs[r][c] = *(const float4*)(g_qkv + (size_t)rowk*(3*EE) + 2*EE + h*32 + c);
        }
        __syncthreads();
        for (int j=0;j<64;j++) {
            float s = 0.f;
            const float4* kr = (const float4*)Ks[j];
            #pragma unroll
            for (int i=0;i<8;i++) {
                float4 k4 = kr[i];
                s = fmaf(qreg[i*4+0], k4.x, s); s = fmaf(qreg[i*4+1], k4.y, s);
                s = fmaf(qreg[i*4+2], k4.z, s); s = fmaf(qreg[i*4+3], k4.w, s);
            }
            if (s > m) {
                float corr = __expf(m - s);
                m = s;
                lsum *= corr;
                #pragma unroll
                for (int i=0;i<32;i++) o[i] *= corr;
            }
            float p = __expf(s - m);
            lsum += p;
            const float4* vr = (const float4*)Vs[j];
            #pragma unroll
            for (int i=0;i<8;i++) {
                float4 v4 = vr[i];
                o[i*4+0] = fmaf(p, v4.x, o[i*4+0]);
                o[i*4+1] = fmaf(p, v4.y, o[i*4+1]);
                o[i*4+2] = fmaf(p, v4.z, o[i*4+2]);
                o[i*4+3] = fmaf(p, v4.w, o[i*4+3]);
            }
        }
    }
    float inv = 1.f / lsum;
    float4* op = (float4*)(g_ctx + (size_t)rowq*EE + h*32);
    #pragma unroll
    for (int i=0;i<8;i++)
        op[i] = make_float4(o[i*4]*inv, o[i*4+1]*inv, o[i*4+2]*inv, o[i*4+3]*inv);
}

// ---------------- residual add + LayerNorm (warp per row, E=256) ----------------
__global__ void add_ln_kernel(const float* __restrict__ x, const float* __restrict__ res,
                              const float* __restrict__ g, const float* __restrict__ bta,
                              float* __restrict__ out) {
    int row  = blockIdx.x * (blockDim.x >> 5) + (threadIdx.x >> 5);
    int lane = threadIdx.x & 31;
    const float4* xp = (const float4*)(x   + (size_t)row*EE);
    const float4* rp = (const float4*)(res + (size_t)row*EE);
    float v[8];
    float4 a0 = xp[lane],     b0 = rp[lane];
    float4 a1 = xp[lane+32],  b1 = rp[lane+32];
    v[0]=a0.x+b0.x; v[1]=a0.y+b0.y; v[2]=a0.z+b0.z; v[3]=a0.w+b0.w;
    v[4]=a1.x+b1.x; v[5]=a1.y+b1.y; v[6]=a1.z+b1.z; v[7]=a1.w+b1.w;
    float s=0.f, s2=0.f;
    #pragma unroll
    for (int i=0;i<8;i++){ s += v[i]; s2 = fmaf(v[i], v[i], s2); }
    #pragma unroll
    for (int off=16; off; off>>=1) {
        s  += __shfl_xor_sync(0xffffffffu, s,  off);
        s2 += __shfl_xor_sync(0xffffffffu, s2, off);
    }
    float mean = s * (1.f/EE);
    float var  = s2 * (1.f/EE) - mean*mean;
    float rstd = rsqrtf(var + 1e-6f);
    float4* op = (float4*)(out + (size_t)row*EE);
    const float4* gp = (const float4*)g;
    const float4* bp = (const float4*)bta;
    float4 g0=gp[lane], g1=gp[lane+32], c0=bp[lane], c1=bp[lane+32];
    op[lane]    = make_float4((v[0]-mean)*rstd*g0.x+c0.x, (v[1]-mean)*rstd*g0.y+c0.y,
                              (v[2]-mean)*rstd*g0.z+c0.z, (v[3]-mean)*rstd*g0.w+c0.w);
    op[lane+32] = make_float4((v[4]-mean)*rstd*g1.x+c1.x, (v[5]-mean)*rstd*g1.y+c1.y,
                              (v[6]-mean)*rstd*g1.z+c1.z, (v[7]-mean)*rstd*g1.w+c1.w);
}

// ---------------- gate: sigmoid(mean_l(seqs) @ mw_w^T + mw_b) per batch ----------------
__global__ void gate_kernel(const float* __restrict__ mw_w, const float* __restrict__ mw_b) {
    int b = blockIdx.x;
    int e = threadIdx.x;           // 256 threads
    float s = 0.f;
    for (int l=0;l<LL;l++) s += g_seqs[(size_t)((b<<9)+l)*EE + e];
    s = (s * (1.f/LL)) * mw_w[e];
    __shared__ float red[256];
    red[e] = s; __syncthreads();
    for (int st=128; st; st>>=1) { if (e < st) red[e] += red[e+st]; __syncthreads(); }
    if (e == 0) g_gate[b] = 1.f / (1.f + __expf(-(red[0] + mw_b[0])));
}

// ---------------- gated combine ----------------
__global__ void combine_kernel() {
    int i = blockIdx.x * blockDim.x + threadIdx.x;   // over MROWS*EE
    int row = i >> 8;
    float w = g_gate[row >> 9];
    g_comb[i] = w * g_mamba[i] + (1.f - w) * g_attnln[i];
}

// ---------------- logits: warp per (b,l), pos & neg dots ----------------
__global__ void logits_kernel(const int* __restrict__ pos, const int* __restrict__ neg,
                              const float* __restrict__ item_emb, float* __restrict__ out) {
    int row  = blockIdx.x * (blockDim.x >> 5) + (threadIdx.x >> 5);
    int lane = threadIdx.x & 31;
    const float4* f = (const float4*)(g_feats + (size_t)row*EE);
    float4 f0 = f[lane], f1 = f[lane+32];
    int pi = __ldg(&pos[row]), ni = __ldg(&neg[row]);
    const float4* pe = (const float4*)(item_emb + (size_t)pi*EE);
    const float4* ne = (const float4*)(item_emb + (size_t)ni*EE);
    float4 p0 = pe[lane], p1 = pe[lane+32];
    float4 n0 = ne[lane], n1 = ne[lane+32];
    float dp = f0.x*p0.x+f0.y*p0.y+f0.z*p0.z+f0.w*p0.w
             + f1.x*p1.x+f1.y*p1.y+f1.z*p1.z+f1.w*p1.w;
    float dn = f0.x*n0.x+f0.y*n0.y+f0.z*n0.z+f0.w*n0.w
             + f1.x*n1.x+f1.y*n1.y+f1.z*n1.z+f1.w*n1.w;
    #pragma unroll
    for (int off=16; off; off>>=1) {
        dp += __shfl_xor_sync(0xffffffffu, dp, off);
        dn += __shfl_xor_sync(0xffffffffu, dn, off);
    }
    if (lane == 0) {
        out[row]         = dp;
        out[MROWS + row] = dn;
    }
}

// ---------------- host ----------------
static float* symaddr(const void* sym) {
    void* p = nullptr;
    cudaGetSymbolAddress(&p, sym);
    return (float*)p;
}

static void gemm(const float* A, int lda, const float* W, const float* bias,
                 float* C, int M, int N, int K, int act) {
    dim3 grid((N + 127) / 128, M / 128);
    gemm_tf32_kernel<<<grid, 256>>>(A, lda, W, bias, C, M, N, K, act);
}

extern "C" void kernel_launch(void* const* d_in, const int* in_sizes, int n_in,
                              void* d_out, int out_size) {
    const int*   log_seqs  = (const int*)  d_in[1];
    const int*   pos_seqs  = (const int*)  d_in[2];
    const int*   neg_seqs  = (const int*)  d_in[3];
    const float* item_emb  = (const float*)d_in[4];
    const float* pos_emb   = (const float*)d_in[5];
    const float* in_proj_w = (const float*)d_in[6];
    const float* conv_w    = (const float*)d_in[7];
    const float* conv_b    = (const float*)d_in[8];
    const float* x_proj_w  = (const float*)d_in[9];
    const float* dt_proj_w = (const float*)d_in[10];
    const float* dt_proj_b = (const float*)d_in[11];
    const float* A_log     = (const float*)d_in[12];
    const float* Dp        = (const float*)d_in[13];
    const float* out_proj_w= (const float*)d_in[14];
    const float* attn_in_w = (const float*)d_in[15];
    const float* attn_in_b = (const float*)d_in[16];
    const float* attn_out_w= (const float*)d_in[17];
    const float* attn_out_b= (const float*)d_in[18];
    const float* ln1_g     = (const float*)d_in[19];
    const float* ln1_b     = (const float*)d_in[20];
    const float* mw_w      = (const float*)d_in[21];
    const float* mw_b      = (const float*)d_in[22];
    const float* ff_w1     = (const float*)d_in[23];
    const float* ff_b1     = (const float*)d_in[24];
    const float* ff_w2     = (const float*)d_in[25];
    const float* ff_b2     = (const float*)d_in[26];
    const float* ln2_g     = (const float*)d_in[27];
    const float* ln2_b     = (const float*)d_in[28];
    float* out = (float*)d_out;

    float* p_seqs   = symaddr(g_seqs);
    float* p_xz     = symaddr(g_xz);
    float* p_uconv  = symaddr(g_uconv);
    float* p_xdbl   = symaddr(g_xdbl);
    float* p_dt     = symaddr(g_dt);
    float* p_ymam   = symaddr(g_ymam);
    float* p_mamba  = symaddr(g_mamba);
    float* p_qkv    = symaddr(g_qkv);
    float* p_ctx    = symaddr(g_ctx);
    float* p_attno  = symaddr(g_attno);
    float* p_attnln = symaddr(g_attnln);
    float* p_comb   = symaddr(g_comb);
    float* p_ffh    = symaddr(g_ffh);
    float* p_ff     = symaddr(g_ff);
    float* p_feats  = symaddr(g_feats);

    // 1. embedding + positional
    embed_kernel<<<(MROWS*EE)/256, 256>>>(log_seqs, item_emb, pos_emb);

    // 2. Mamba branch
    gemm(p_seqs, EE, in_proj_w, nullptr, p_xz, MROWS, 2*DI, EE, 0);
    conv_silu_kernel<<<(MROWS*DI)/256, 256>>>(conv_w, conv_b);
    gemm(p_uconv, DI, x_proj_w, nullptr, p_xdbl, MROWS, DTR+2*NN, DI, 0);
    gemm(p_xdbl, 80, dt_proj_w, dt_proj_b, p_dt, MROWS, DI, DTR, 2);  // softplus
    scan2_kernel<<<BB*4, 128>>>(A_log, Dp);
    gemm(p_ymam, DI, out_proj_w, nullptr, p_mamba, MROWS, EE, DI, 0);

    // 3. attention branch
    gemm(p_seqs, EE, attn_in_w, attn_in_b, p_qkv, MROWS, 3*EE, EE, 0);
    attn_kernel<<<BB*HH, 512>>>();
    gemm(p_ctx, EE, attn_out_w, attn_out_b, p_attno, MROWS, EE, EE, 0);
    add_ln_kernel<<<MROWS/8, 256>>>(p_attno, p_seqs, ln1_g, ln1_b, p_attnln);

    // 4. gate + combine
    gate_kernel<<<BB, 256>>>(mw_w, mw_b);
    combine_kernel<<<(MROWS*EE)/256, 256>>>();

    // 5. FFN + LN
    gemm(p_comb, EE, ff_w1, ff_b1, p_ffh, MROWS, 4*EE, EE, 1);       // relu
    gemm(p_ffh, 4*EE, ff_w2, ff_b2, p_ff, MROWS, EE, 4*EE, 0);
    add_ln_kernel<<<MROWS/8, 256>>>(p_ff, p_comb, ln2_g, ln2_b, p_feats);

    // 6. logits
    logits_kernel<<<MROWS/8, 256>>>(pos_seqs, neg_seqs, item_emb, out);
}